// round 4
// baseline (speedup 1.0000x reference)
#include <cuda_runtime.h>

#define BB   4
#define CC   32
#define HH   256
#define WW   256
#define SSZ  16     // stoken size
#define NHH  16
#define NWW  16
#define SP   256    // NHH*NWW superpixels
#define NPIX 65536  // HH*WW

// Deterministic scratch (no atomics anywhere)
__device__ float g_cent[BB][SP][CC];
__device__ float g_pnum[BB][SP][9][CC];
__device__ float g_pden[BB][SP][9];
__device__ float g_aff[BB][9][NPIX];   // k-major iter-1 affinities (9.4 MB)

// ---------------------------------------------------------------------------
// Kernel A: initial centroids = 16x16 block means. One block per (b, s).
// ---------------------------------------------------------------------------
__global__ void k_cent_init(const float* __restrict__ x) {
    int bs = blockIdx.x;
    int b = bs >> 8, s = bs & 255;
    int sy = s >> 4, sx = s & 15;
    int t = threadIdx.x, warp = t >> 5, lane = t & 31;
    const float* xb = x + (size_t)b * CC * NPIX;
#pragma unroll
    for (int ci = 0; ci < 4; ci++) {
        int c = warp + ci * 8;
        const float* p = xb + (size_t)c * NPIX
                       + (size_t)(sy * SSZ + (lane >> 1)) * WW
                       + sx * SSZ + (lane & 1) * 8;
        float sum = 0.f;
#pragma unroll
        for (int i = 0; i < 8; i++) sum += p[i];
#pragma unroll
        for (int o = 16; o > 0; o >>= 1)
            sum += __shfl_down_sync(0xffffffffu, sum, o);
        if (lane == 0) g_cent[b][s][c] = sum * (1.f / 256.f);
    }
}

// ---------------------------------------------------------------------------
// Kernel B: iteration 0. One block per (b, tile). 288 threads (9 warps).
// Tile-local softmax + reduction into unique per-(sp,dir) slots (deterministic).
// ---------------------------------------------------------------------------
__global__ void k_iter0(const float* __restrict__ x) {
    __shared__ float px_sh[256][33];
    __shared__ float cent_sh[9][32];
    __shared__ float aff_sh[256][9];

    int b = blockIdx.y, s = blockIdx.x;
    int sy = s >> 4, sx = s & 15;
    int t = threadIdx.x;

    if (t < 256) {
        const float* xp = x + (size_t)b * CC * NPIX
                        + (size_t)(sy * SSZ + (t >> 4)) * WW
                        + sx * SSZ + (t & 15);
#pragma unroll
        for (int c = 0; c < CC; c++) px_sh[t][c] = xp[(size_t)c * NPIX];
    }
    {   // t in [0,288): k = t>>5, c = t&31
        int k = t >> 5, c = t & 31;
        int ny = sy + k / 3 - 1, nx = sx + k % 3 - 1;
        bool v = ((unsigned)ny < NHH) & ((unsigned)nx < NWW);
        cent_sh[k][c] = v ? g_cent[b][ny * NWW + nx][c] : 0.f;
    }
    __syncthreads();

    if (t < 256) {
        float pv[CC];
#pragma unroll
        for (int c = 0; c < CC; c++) pv[c] = px_sh[t][c];
        float d[9];
#pragma unroll
        for (int k = 0; k < 9; k++) {
            float acc = 0.f;
#pragma unroll
            for (int c = 0; c < CC; c++) {
                float df = pv[c] - cent_sh[k][c];
                acc = fmaf(df, df, acc);
            }
            d[k] = acc;
        }
        float dmin = 3.4e38f;
#pragma unroll
        for (int k = 0; k < 9; k++) {
            int ny = sy + k / 3 - 1, nx = sx + k % 3 - 1;
            bool v = ((unsigned)ny < NHH) & ((unsigned)nx < NWW);
            if (v && d[k] < dmin) dmin = d[k];
        }
        float e[9], sum = 0.f;
#pragma unroll
        for (int k = 0; k < 9; k++) {
            int ny = sy + k / 3 - 1, nx = sx + k % 3 - 1;
            bool v = ((unsigned)ny < NHH) & ((unsigned)nx < NWW);
            e[k] = v ? expf(dmin - d[k]) : 0.f;
            sum += e[k];
        }
        float inv = 1.f / sum;
#pragma unroll
        for (int k = 0; k < 9; k++) aff_sh[t][k] = e[k] * inv;
    }
    __syncthreads();

    {   // Phase C: warp = neighbor k, lane = channel c
        int k = t >> 5, c = t & 31;
        int ny = sy + k / 3 - 1, nx = sx + k % 3 - 1;
        bool v = ((unsigned)ny < NHH) & ((unsigned)nx < NWW);
        if (v) {
            int ns = ny * NWW + nx;
            float acc = 0.f;
            for (int p = 0; p < 256; p++)
                acc = fmaf(aff_sh[p][k], px_sh[p][c], acc);
            g_pnum[b][ns][k][c] = acc;
            float dacc = 0.f;
            for (int p = c; p < 256; p += 32) dacc += aff_sh[p][k];
#pragma unroll
            for (int o = 16; o > 0; o >>= 1)
                dacc += __shfl_down_sync(0xffffffffu, dacc, o);
            if (c == 0) g_pden[b][ns][k] = dacc;
        }
    }
}

// ---------------------------------------------------------------------------
// Kernel C: centroid update from slots. Fixed order -> deterministic.
// ---------------------------------------------------------------------------
__global__ void k_cent_update() {
    int bs = blockIdx.x;
    int b = bs >> 8, s = bs & 255;
    int sy = s >> 4, sx = s & 15;
    int c = threadIdx.x;
    float num = 0.f, den = 0.f;
#pragma unroll
    for (int k = 0; k < 9; k++) {
        int ty = sy - (k / 3 - 1), tx = sx - (k % 3 - 1);
        if (((unsigned)ty < NHH) & ((unsigned)tx < NWW)) {
            num += g_pnum[b][s][k][c];
            den += g_pden[b][s][k];
        }
    }
    g_cent[b][s][c] = num / (den + 1e-16f);
}

// ---------------------------------------------------------------------------
// Kernel D: iteration 1 -> compact k-major affinities g_aff[b][k][n].
// One block per (b, tile), 256 threads = pixels. 64B-coalesced segments.
// ---------------------------------------------------------------------------
__global__ void k_aff1(const float* __restrict__ x) {
    __shared__ float px_sh[256][33];
    __shared__ float cent_sh[9][32];

    int b = blockIdx.y, s = blockIdx.x;
    int sy = s >> 4, sx = s & 15;
    int t = threadIdx.x;

    {
        const float* xp = x + (size_t)b * CC * NPIX
                        + (size_t)(sy * SSZ + (t >> 4)) * WW
                        + sx * SSZ + (t & 15);
#pragma unroll
        for (int c = 0; c < CC; c++) px_sh[t][c] = xp[(size_t)c * NPIX];
    }
    for (int i = t; i < 288; i += 256) {
        int k = i >> 5, c = i & 31;
        int ny = sy + k / 3 - 1, nx = sx + k % 3 - 1;
        bool v = ((unsigned)ny < NHH) & ((unsigned)nx < NWW);
        cent_sh[k][c] = v ? g_cent[b][ny * NWW + nx][c] : 0.f;
    }
    __syncthreads();

    float pv[CC];
#pragma unroll
    for (int c = 0; c < CC; c++) pv[c] = px_sh[t][c];
    float d[9];
#pragma unroll
    for (int k = 0; k < 9; k++) {
        float acc = 0.f;
#pragma unroll
        for (int c = 0; c < CC; c++) {
            float df = pv[c] - cent_sh[k][c];
            acc = fmaf(df, df, acc);
        }
        d[k] = acc;
    }
    float dmin = 3.4e38f;
#pragma unroll
    for (int k = 0; k < 9; k++) {
        int ny = sy + k / 3 - 1, nx = sx + k % 3 - 1;
        bool v = ((unsigned)ny < NHH) & ((unsigned)nx < NWW);
        if (v && d[k] < dmin) dmin = d[k];
    }
    float e[9], sum = 0.f;
#pragma unroll
    for (int k = 0; k < 9; k++) {
        int ny = sy + k / 3 - 1, nx = sx + k % 3 - 1;
        bool v = ((unsigned)ny < NHH) & ((unsigned)nx < NWW);
        e[k] = v ? expf(dmin - d[k]) : 0.f;
        sum += e[k];
    }
    float inv = 1.f / sum;

    int n = (sy * SSZ + (t >> 4)) * WW + sx * SSZ + (t & 15);
#pragma unroll
    for (int k = 0; k < 9; k++) {
        int ny = sy + k / 3 - 1, nx = sx + k % 3 - 1;
        bool v = ((unsigned)ny < NHH) & ((unsigned)nx < NWW);
        if (v) g_aff[b][k][n] = e[k] * inv;
    }
}

// ---------------------------------------------------------------------------
// Kernel E: single-pass output fill. One block per (b, sp) owns the full
// 65536-float output row: zeros outside the 3x3-tile window, affinities
// inside. Every element stored exactly once (float4) -> no memset pass.
// ---------------------------------------------------------------------------
__global__ void k_fill(float* __restrict__ out) {
    int b = blockIdx.y, s = blockIdx.x;
    int sy = s >> 4, sx = s & 15;
    float4* orow = (float4*)(out + ((size_t)b * SP + s) * NPIX);
    const float* affb = &g_aff[b][0][0];
    const float4 z = make_float4(0.f, 0.f, 0.f, 0.f);
    int t = threadIdx.x;
#pragma unroll 4
    for (int i = t; i < NPIX / 4; i += 256) {
        int y  = i >> 6;            // pixel row
        int j  = i & 63;            // float4 column
        int x  = j << 2;
        int kdy = sy - (y >> 4) + 1;
        int kdx = sx - (x >> 4) + 1;
        float4 v = z;
        if (((unsigned)kdy < 3u) & ((unsigned)kdx < 3u)) {
            int k = kdy * 3 + kdx;
            v = *(const float4*)(affb + (size_t)k * NPIX + (y << 8) + x);
        }
        orow[i] = v;
    }
}

// Tail fill (if output encodes trailing S=256 scalar after abs_aff)
__global__ void k_tail(float* __restrict__ p, int n) {
    int i = blockIdx.x * blockDim.x + threadIdx.x;
    if (i < n) p[i] = 256.0f;
}

extern "C" void kernel_launch(void* const* d_in, const int* in_sizes, int n_in,
                              void* d_out, int out_size) {
    const float* x = (const float*)d_in[0];
    float* out = (float*)d_out;

    dim3 grid(SP, BB);
    k_cent_init<<<BB * SP, 256>>>(x);
    k_iter0<<<grid, 288>>>(x);
    k_cent_update<<<BB * SP, 32>>>();
    k_aff1<<<grid, 256>>>(x);
    k_fill<<<grid, 256>>>(out);

    long long total = (long long)BB * SP * NPIX;
    if ((long long)out_size > total) {
        int tail = (int)((long long)out_size - total);
        k_tail<<<(tail + 255) / 256, 256>>>(out + total, tail);
    }
}

// round 5
// speedup vs baseline: 1.1392x; 1.1392x over previous
#include <cuda_runtime.h>

#define BB   4
#define CC   32
#define HH   256
#define WW   256
#define SSZ  16
#define NHH  16
#define NWW  16
#define SP   256
#define NPIX 65536

__device__ float g_cent[BB][SP][CC];
__device__ float g_pnum[BB][SP][9][CC];
__device__ float g_pden[BB][SP][9];
__device__ float g_aff[BB][9][NPIX];   // k-major iter-1 affinities (9.4 MB)

// ---------------------------------------------------------------------------
// A: initial centroids = 16x16 block means. One block per (b, s).
// ---------------------------------------------------------------------------
__global__ void k_cent_init(const float* __restrict__ x) {
    int bs = blockIdx.x;
    int b = bs >> 8, s = bs & 255;
    int sy = s >> 4, sx = s & 15;
    int t = threadIdx.x, warp = t >> 5, lane = t & 31;
    const float* xb = x + (size_t)b * CC * NPIX;
#pragma unroll
    for (int ci = 0; ci < 4; ci++) {
        int c = warp + ci * 8;
        const float* p = xb + (size_t)c * NPIX
                       + (size_t)(sy * SSZ + (lane >> 1)) * WW
                       + sx * SSZ + (lane & 1) * 8;
        float sum = 0.f;
#pragma unroll
        for (int i = 0; i < 8; i++) sum += p[i];
#pragma unroll
        for (int o = 16; o > 0; o >>= 1)
            sum += __shfl_down_sync(0xffffffffu, sum, o);
        if (lane == 0) g_cent[b][s][c] = sum * (1.f / 256.f);
    }
}

// ---------------------------------------------------------------------------
// B: iteration 0.  288 threads. Broadcast-float4 smem ops; dot-form distance.
// ---------------------------------------------------------------------------
__global__ void k_iter0(const float* __restrict__ x) {
    __shared__ __align__(16) float px_sh[256][33];
    __shared__ __align__(16) float cent_sh[9][32];
    __shared__ __align__(16) float aff_sh[9][260];   // k-major, 16B-aligned rows
    __shared__ float cnorm_sh[9];
    __shared__ float denp_sh[8][9];

    int b = blockIdx.y, s = blockIdx.x;
    int sy = s >> 4, sx = s & 15;
    int t = threadIdx.x;
    int w = t >> 5, lane = t & 31;

    if (t < 256) {
        const float* xp = x + (size_t)b * CC * NPIX
                        + (size_t)(sy * SSZ + (t >> 4)) * WW
                        + sx * SSZ + (t & 15);
#pragma unroll
        for (int c = 0; c < CC; c++) px_sh[t][c] = xp[(size_t)c * NPIX];
    }
    {   // warp w = neighbor k, lane = channel; also compute |c_k|^2
        int ny = sy + w / 3 - 1, nx = sx + w % 3 - 1;
        bool v = ((unsigned)ny < NHH) & ((unsigned)nx < NWW);
        float cv = v ? g_cent[b][ny * NWW + nx][lane] : 0.f;
        cent_sh[w][lane] = cv;
        float cn = cv * cv;
#pragma unroll
        for (int o = 16; o > 0; o >>= 1)
            cn += __shfl_down_sync(0xffffffffu, cn, o);
        if (lane == 0) cnorm_sh[w] = cn;
    }
    __syncthreads();

    if (t < 256) {
        float dot[9];
#pragma unroll
        for (int k = 0; k < 9; k++) dot[k] = 0.f;
        float pnorm = 0.f;
#pragma unroll
        for (int c4 = 0; c4 < 8; c4++) {
            int cb = c4 * 4;
            float p0 = px_sh[t][cb],     p1 = px_sh[t][cb + 1];
            float p2 = px_sh[t][cb + 2], p3 = px_sh[t][cb + 3];
            pnorm = fmaf(p0, p0, fmaf(p1, p1, fmaf(p2, p2, fmaf(p3, p3, pnorm))));
#pragma unroll
            for (int k = 0; k < 9; k++) {
                const float4 cv = *(const float4*)&cent_sh[k][cb];  // broadcast
                dot[k] = fmaf(p0, cv.x, fmaf(p1, cv.y, fmaf(p2, cv.z, fmaf(p3, cv.w, dot[k]))));
            }
        }
        float d[9], dmin = 3.4e38f;
#pragma unroll
        for (int k = 0; k < 9; k++) {
            int ny = sy + k / 3 - 1, nx = sx + k % 3 - 1;
            bool v = ((unsigned)ny < NHH) & ((unsigned)nx < NWW);
            d[k] = fmaf(-2.f, dot[k], pnorm) + cnorm_sh[k];
            if (v && d[k] < dmin) dmin = d[k];
        }
        float e[9], sum = 0.f;
#pragma unroll
        for (int k = 0; k < 9; k++) {
            int ny = sy + k / 3 - 1, nx = sx + k % 3 - 1;
            bool v = ((unsigned)ny < NHH) & ((unsigned)nx < NWW);
            e[k] = v ? expf(dmin - d[k]) : 0.f;
            sum += e[k];
        }
        float inv = 1.f / sum;
#pragma unroll
        for (int k = 0; k < 9; k++) aff_sh[k][t] = e[k] * inv;
    }
    __syncthreads();

    // Phase C: 8 warps x 32 pixels x 9 dirs; lane = channel
    float acc[9];
#pragma unroll
    for (int k = 0; k < 9; k++) acc[k] = 0.f;
    if (t < 256) {
#pragma unroll
        for (int pg = 0; pg < 8; pg++) {
            int p = (w << 5) + (pg << 2);
            float p0 = px_sh[p][lane],     p1 = px_sh[p + 1][lane];
            float p2 = px_sh[p + 2][lane], p3 = px_sh[p + 3][lane];
#pragma unroll
            for (int k = 0; k < 9; k++) {
                const float4 a4 = *(const float4*)&aff_sh[k][p];    // broadcast
                acc[k] = fmaf(a4.x, p0, fmaf(a4.y, p1, fmaf(a4.z, p2, fmaf(a4.w, p3, acc[k]))));
            }
        }
        float dp[9];
#pragma unroll
        for (int k = 0; k < 9; k++) {
            float v = aff_sh[k][(w << 5) + lane];
#pragma unroll
            for (int o = 16; o > 0; o >>= 1)
                v += __shfl_down_sync(0xffffffffu, v, o);
            dp[k] = v;
        }
        if (lane == 0) {
#pragma unroll
            for (int k = 0; k < 9; k++) denp_sh[w][k] = dp[k];
        }
    }
    __syncthreads();
    float* part = &px_sh[0][0];          // reuse px_sh as partial buffer
    if (t < 256) {
#pragma unroll
        for (int k = 0; k < 9; k++) part[(w * 9 + k) * 32 + lane] = acc[k];
    }
    __syncthreads();
    {   // warp w = dir k, lane = channel: final reduce + slot writes
        int ny = sy + w / 3 - 1, nx = sx + w % 3 - 1;
        bool v = ((unsigned)ny < NHH) & ((unsigned)nx < NWW);
        if (v) {
            int ns = ny * NWW + nx;
            float num = 0.f;
#pragma unroll
            for (int ww = 0; ww < 8; ww++) num += part[(ww * 9 + w) * 32 + lane];
            g_pnum[b][ns][w][lane] = num;
            if (lane == 0) {
                float den = 0.f;
#pragma unroll
                for (int ww = 0; ww < 8; ww++) den += denp_sh[ww][w];
                g_pden[b][ns][w] = den;
            }
        }
    }
}

// ---------------------------------------------------------------------------
// C: centroid update from slots. Fixed order -> deterministic.
// ---------------------------------------------------------------------------
__global__ void k_cent_update() {
    int bs = blockIdx.x;
    int b = bs >> 8, s = bs & 255;
    int sy = s >> 4, sx = s & 15;
    int c = threadIdx.x;
    float num = 0.f, den = 0.f;
#pragma unroll
    for (int k = 0; k < 9; k++) {
        int ty = sy - (k / 3 - 1), tx = sx - (k % 3 - 1);
        if (((unsigned)ty < NHH) & ((unsigned)tx < NWW)) {
            num += g_pnum[b][s][k][c];
            den += g_pden[b][s][k];
        }
    }
    g_cent[b][s][c] = num / (den + 1e-16f);
}

// ---------------------------------------------------------------------------
// D: iteration 1 -> compact k-major affinities g_aff[b][k][n]. 288 threads.
// ---------------------------------------------------------------------------
__global__ void k_aff1(const float* __restrict__ x) {
    __shared__ __align__(16) float px_sh[256][33];
    __shared__ __align__(16) float cent_sh[9][32];
    __shared__ float cnorm_sh[9];

    int b = blockIdx.y, s = blockIdx.x;
    int sy = s >> 4, sx = s & 15;
    int t = threadIdx.x;
    int w = t >> 5, lane = t & 31;

    if (t < 256) {
        const float* xp = x + (size_t)b * CC * NPIX
                        + (size_t)(sy * SSZ + (t >> 4)) * WW
                        + sx * SSZ + (t & 15);
#pragma unroll
        for (int c = 0; c < CC; c++) px_sh[t][c] = xp[(size_t)c * NPIX];
    }
    {
        int ny = sy + w / 3 - 1, nx = sx + w % 3 - 1;
        bool v = ((unsigned)ny < NHH) & ((unsigned)nx < NWW);
        float cv = v ? g_cent[b][ny * NWW + nx][lane] : 0.f;
        cent_sh[w][lane] = cv;
        float cn = cv * cv;
#pragma unroll
        for (int o = 16; o > 0; o >>= 1)
            cn += __shfl_down_sync(0xffffffffu, cn, o);
        if (lane == 0) cnorm_sh[w] = cn;
    }
    __syncthreads();

    if (t < 256) {
        float dot[9];
#pragma unroll
        for (int k = 0; k < 9; k++) dot[k] = 0.f;
        float pnorm = 0.f;
#pragma unroll
        for (int c4 = 0; c4 < 8; c4++) {
            int cb = c4 * 4;
            float p0 = px_sh[t][cb],     p1 = px_sh[t][cb + 1];
            float p2 = px_sh[t][cb + 2], p3 = px_sh[t][cb + 3];
            pnorm = fmaf(p0, p0, fmaf(p1, p1, fmaf(p2, p2, fmaf(p3, p3, pnorm))));
#pragma unroll
            for (int k = 0; k < 9; k++) {
                const float4 cv = *(const float4*)&cent_sh[k][cb];
                dot[k] = fmaf(p0, cv.x, fmaf(p1, cv.y, fmaf(p2, cv.z, fmaf(p3, cv.w, dot[k]))));
            }
        }
        float d[9], dmin = 3.4e38f;
#pragma unroll
        for (int k = 0; k < 9; k++) {
            int ny = sy + k / 3 - 1, nx = sx + k % 3 - 1;
            bool v = ((unsigned)ny < NHH) & ((unsigned)nx < NWW);
            d[k] = fmaf(-2.f, dot[k], pnorm) + cnorm_sh[k];
            if (v && d[k] < dmin) dmin = d[k];
        }
        float e[9], sum = 0.f;
#pragma unroll
        for (int k = 0; k < 9; k++) {
            int ny = sy + k / 3 - 1, nx = sx + k % 3 - 1;
            bool v = ((unsigned)ny < NHH) & ((unsigned)nx < NWW);
            e[k] = v ? expf(dmin - d[k]) : 0.f;
            sum += e[k];
        }
        float inv = 1.f / sum;
        int n = (sy * SSZ + (t >> 4)) * WW + sx * SSZ + (t & 15);
#pragma unroll
        for (int k = 0; k < 9; k++) {
            int ny = sy + k / 3 - 1, nx = sx + k % 3 - 1;
            bool v = ((unsigned)ny < NHH) & ((unsigned)nx < NWW);
            if (v) g_aff[b][k][n] = e[k] * inv;
        }
    }
}

// ---------------------------------------------------------------------------
// E1: zero region of out (everything outside each sp's 3x3-tile rect).
// Runs on a FORKED stream, independent of all compute. Streaming stores.
// ---------------------------------------------------------------------------
__global__ void k_zero(float* __restrict__ out) {
    int b = blockIdx.y, s = blockIdx.x;
    int sy = s >> 4, sx = s & 15;
    int ny0 = max(sy - 1, 0), ny1 = min(sy + 1, NHH - 1);
    int nx0 = max(sx - 1, 0), nx1 = min(sx + 1, NWW - 1);
    int y0 = ny0 << 4, y1 = (ny1 + 1) << 4;
    int x0 = nx0 << 4, x1 = (nx1 + 1) << 4;
    float4* orow = (float4*)(out + ((size_t)b * SP + s) * NPIX);
    const float4 z = make_float4(0.f, 0.f, 0.f, 0.f);
    int t = threadIdx.x;
#pragma unroll 8
    for (int i = t; i < NPIX / 4; i += 256) {
        int y = i >> 6;
        int xf = (i & 63) << 2;
        bool inrect = (y >= y0) & (y < y1) & (xf >= x0) & (xf < x1);
        if (!inrect) __stcs(orow + i, z);
    }
}

// ---------------------------------------------------------------------------
// E2: fill each sp's nonzero rect from g_aff (after k_aff1). Disjoint from E1.
// ---------------------------------------------------------------------------
__global__ void k_window(float* __restrict__ out) {
    int b = blockIdx.y, s = blockIdx.x;
    int sy = s >> 4, sx = s & 15;
    int ny0 = max(sy - 1, 0), ny1 = min(sy + 1, NHH - 1);
    int nx0 = max(sx - 1, 0), nx1 = min(sx + 1, NWW - 1);
    int W4 = (nx1 - nx0 + 1) << 2;         // float4 per rect row
    int Hr = (ny1 - ny0 + 1) << 4;         // rect rows
    int total = W4 * Hr;
    float* orow = out + ((size_t)b * SP + s) * NPIX;
    const float* affb = &g_aff[b][0][0];
    for (int i = threadIdx.x; i < total; i += 256) {
        int ry = i / W4, rx = i - ry * W4;
        int y = (ny0 << 4) + ry;
        int xx = (nx0 << 4) + (rx << 2);
        int ty = y >> 4, tx = xx >> 4;
        int k = (sy - ty + 1) * 3 + (sx - tx + 1);
        float4 v = *(const float4*)(affb + (size_t)k * NPIX + (y << 8) + xx);
        *(float4*)(orow + (y << 8) + xx) = v;
    }
}

__global__ void k_tail(float* __restrict__ p, int n) {
    int i = blockIdx.x * blockDim.x + threadIdx.x;
    if (i < n) p[i] = 256.0f;
}

extern "C" void kernel_launch(void* const* d_in, const int* in_sizes, int n_in,
                              void* d_out, int out_size) {
    const float* x = (const float*)d_in[0];
    float* out = (float*)d_out;
    dim3 grid(SP, BB);

    // Fork a side stream: k_zero has no data dependencies -> overlap with compute.
    cudaStream_t s2;
    cudaStreamCreateWithFlags(&s2, cudaStreamNonBlocking);
    cudaEvent_t e1, e2;
    cudaEventCreateWithFlags(&e1, cudaEventDisableTiming);
    cudaEventCreateWithFlags(&e2, cudaEventDisableTiming);

    cudaEventRecord(e1, 0);
    cudaStreamWaitEvent(s2, e1, 0);
    k_zero<<<grid, 256, 0, s2>>>(out);
    cudaEventRecord(e2, s2);

    k_cent_init<<<BB * SP, 256>>>(x);
    k_iter0<<<grid, 288>>>(x);
    k_cent_update<<<BB * SP, 32>>>();
    k_aff1<<<grid, 288>>>(x);
    k_window<<<grid, 256>>>(out);          // disjoint from k_zero's writes
    cudaStreamWaitEvent(0, e2, 0);         // join side branch

    long long total = (long long)BB * SP * NPIX;
    if ((long long)out_size > total) {
        int tail = (int)((long long)out_size - total);
        k_tail<<<(tail + 255) / 256, 256>>>(out + total, tail);
    }

    // Destroy only when not capturing (destroying a capture-associated stream
    // can invalidate the graph; the one capture call leaks 1 stream + 2 events).
    cudaStreamCaptureStatus cs = cudaStreamCaptureStatusNone;
    cudaStreamIsCapturing(0, &cs);
    if (cs == cudaStreamCaptureStatusNone) {
        cudaEventDestroy(e1);
        cudaEventDestroy(e2);
        cudaStreamDestroy(s2);
    }
}

// round 6
// speedup vs baseline: 1.2224x; 1.0730x over previous
#include <cuda_runtime.h>

#define BB   4
#define CC   32
#define HH   256
#define WW   256
#define SSZ  16
#define NHH  16
#define NWW  16
#define SP   256
#define NPIX 65536

__device__ float g_cent[BB][SP][CC];
__device__ float g_pnum[BB][SP][9][CC];
__device__ float g_pden[BB][SP][9];

// ---------------------------------------------------------------------------
// A: initial centroids = 16x16 block means. One block per (b, s).
// ---------------------------------------------------------------------------
__global__ void k_cent_init(const float* __restrict__ x) {
    int bs = blockIdx.x;
    int b = bs >> 8, s = bs & 255;
    int sy = s >> 4, sx = s & 15;
    int t = threadIdx.x, warp = t >> 5, lane = t & 31;
    const float* xb = x + (size_t)b * CC * NPIX;
#pragma unroll
    for (int ci = 0; ci < 4; ci++) {
        int c = warp + ci * 8;
        const float* p = xb + (size_t)c * NPIX
                       + (size_t)(sy * SSZ + (lane >> 1)) * WW
                       + sx * SSZ + (lane & 1) * 8;
        float sum = 0.f;
#pragma unroll
        for (int i = 0; i < 8; i++) sum += p[i];
#pragma unroll
        for (int o = 16; o > 0; o >>= 1)
            sum += __shfl_down_sync(0xffffffffu, sum, o);
        if (lane == 0) g_cent[b][s][c] = sum * (1.f / 256.f);
    }
}

// ---------------------------------------------------------------------------
// B: iteration 0.  288 threads. Broadcast-float4 smem ops; dot-form distance.
// Writes per-(sp,dir) partial sums to unique slots (deterministic).
// ---------------------------------------------------------------------------
__global__ void k_iter0(const float* __restrict__ x) {
    __shared__ __align__(16) float px_sh[256][33];
    __shared__ __align__(16) float cent_sh[9][32];
    __shared__ __align__(16) float aff_sh[9][260];
    __shared__ float cnorm_sh[9];
    __shared__ float denp_sh[8][9];

    int b = blockIdx.y, s = blockIdx.x;
    int sy = s >> 4, sx = s & 15;
    int t = threadIdx.x;
    int w = t >> 5, lane = t & 31;

    if (t < 256) {
        const float* xp = x + (size_t)b * CC * NPIX
                        + (size_t)(sy * SSZ + (t >> 4)) * WW
                        + sx * SSZ + (t & 15);
#pragma unroll
        for (int c = 0; c < CC; c++) px_sh[t][c] = xp[(size_t)c * NPIX];
    }
    {   // warp w = neighbor k, lane = channel; also |c_k|^2
        int ny = sy + w / 3 - 1, nx = sx + w % 3 - 1;
        bool v = ((unsigned)ny < NHH) & ((unsigned)nx < NWW);
        float cv = v ? g_cent[b][ny * NWW + nx][lane] : 0.f;
        cent_sh[w][lane] = cv;
        float cn = cv * cv;
#pragma unroll
        for (int o = 16; o > 0; o >>= 1)
            cn += __shfl_down_sync(0xffffffffu, cn, o);
        if (lane == 0) cnorm_sh[w] = cn;
    }
    __syncthreads();

    if (t < 256) {
        float dot[9];
#pragma unroll
        for (int k = 0; k < 9; k++) dot[k] = 0.f;
        float pnorm = 0.f;
#pragma unroll
        for (int c4 = 0; c4 < 8; c4++) {
            int cb = c4 * 4;
            float p0 = px_sh[t][cb],     p1 = px_sh[t][cb + 1];
            float p2 = px_sh[t][cb + 2], p3 = px_sh[t][cb + 3];
            pnorm = fmaf(p0, p0, fmaf(p1, p1, fmaf(p2, p2, fmaf(p3, p3, pnorm))));
#pragma unroll
            for (int k = 0; k < 9; k++) {
                const float4 cv = *(const float4*)&cent_sh[k][cb];
                dot[k] = fmaf(p0, cv.x, fmaf(p1, cv.y, fmaf(p2, cv.z, fmaf(p3, cv.w, dot[k]))));
            }
        }
        float d[9], dmin = 3.4e38f;
#pragma unroll
        for (int k = 0; k < 9; k++) {
            int ny = sy + k / 3 - 1, nx = sx + k % 3 - 1;
            bool v = ((unsigned)ny < NHH) & ((unsigned)nx < NWW);
            d[k] = fmaf(-2.f, dot[k], pnorm) + cnorm_sh[k];
            if (v && d[k] < dmin) dmin = d[k];
        }
        float e[9], sum = 0.f;
#pragma unroll
        for (int k = 0; k < 9; k++) {
            int ny = sy + k / 3 - 1, nx = sx + k % 3 - 1;
            bool v = ((unsigned)ny < NHH) & ((unsigned)nx < NWW);
            e[k] = v ? expf(dmin - d[k]) : 0.f;
            sum += e[k];
        }
        float inv = 1.f / sum;
#pragma unroll
        for (int k = 0; k < 9; k++) aff_sh[k][t] = e[k] * inv;
    }
    __syncthreads();

    float acc[9];
#pragma unroll
    for (int k = 0; k < 9; k++) acc[k] = 0.f;
    if (t < 256) {
#pragma unroll
        for (int pg = 0; pg < 8; pg++) {
            int p = (w << 5) + (pg << 2);
            float p0 = px_sh[p][lane],     p1 = px_sh[p + 1][lane];
            float p2 = px_sh[p + 2][lane], p3 = px_sh[p + 3][lane];
#pragma unroll
            for (int k = 0; k < 9; k++) {
                const float4 a4 = *(const float4*)&aff_sh[k][p];
                acc[k] = fmaf(a4.x, p0, fmaf(a4.y, p1, fmaf(a4.z, p2, fmaf(a4.w, p3, acc[k]))));
            }
        }
        float dp[9];
#pragma unroll
        for (int k = 0; k < 9; k++) {
            float v = aff_sh[k][(w << 5) + lane];
#pragma unroll
            for (int o = 16; o > 0; o >>= 1)
                v += __shfl_down_sync(0xffffffffu, v, o);
            dp[k] = v;
        }
        if (lane == 0) {
#pragma unroll
            for (int k = 0; k < 9; k++) denp_sh[w][k] = dp[k];
        }
    }
    __syncthreads();
    float* part = &px_sh[0][0];          // reuse px_sh
    if (t < 256) {
#pragma unroll
        for (int k = 0; k < 9; k++) part[(w * 9 + k) * 32 + lane] = acc[k];
    }
    __syncthreads();
    {   // warp w = dir k, lane = channel: final reduce + slot writes
        int ny = sy + w / 3 - 1, nx = sx + w % 3 - 1;
        bool v = ((unsigned)ny < NHH) & ((unsigned)nx < NWW);
        if (v) {
            int ns = ny * NWW + nx;
            float num = 0.f;
#pragma unroll
            for (int ww = 0; ww < 8; ww++) num += part[(ww * 9 + w) * 32 + lane];
            g_pnum[b][ns][w][lane] = num;
            if (lane == 0) {
                float den = 0.f;
#pragma unroll
                for (int ww = 0; ww < 8; ww++) den += denp_sh[ww][w];
                g_pden[b][ns][w] = den;
            }
        }
    }
}

// ---------------------------------------------------------------------------
// D: iteration 1, fused: recompute neighbor centroids from slots (L2-resident),
// then distances/softmax, then write affinities DIRECTLY into out windows.
// 288 threads. Writes are 64B segments (16 lanes contiguous).
// ---------------------------------------------------------------------------
__global__ void k_aff_out(const float* __restrict__ x, float* __restrict__ out) {
    __shared__ __align__(16) float px_sh[256][33];
    __shared__ __align__(16) float cent_sh[9][32];
    __shared__ float cnorm_sh[9];

    int b = blockIdx.y, s = blockIdx.x;
    int sy = s >> 4, sx = s & 15;
    int t = threadIdx.x;
    int w = t >> 5, lane = t & 31;

    if (t < 256) {
        const float* xp = x + (size_t)b * CC * NPIX
                        + (size_t)(sy * SSZ + (t >> 4)) * WW
                        + sx * SSZ + (t & 15);
#pragma unroll
        for (int c = 0; c < CC; c++) px_sh[t][c] = xp[(size_t)c * NPIX];
    }
    {   // warp w = neighbor; compute its UPDATED centroid from slots
        int ny = sy + w / 3 - 1, nx = sx + w % 3 - 1;
        bool v = ((unsigned)ny < NHH) & ((unsigned)nx < NWW);
        float cv = 0.f;
        if (v) {
            int ns = ny * NWW + nx;
            float num = 0.f;
#pragma unroll
            for (int k = 0; k < 9; k++) {
                int ty = ny - (k / 3 - 1), tx = nx - (k % 3 - 1);
                if (((unsigned)ty < NHH) & ((unsigned)tx < NWW))
                    num += g_pnum[b][ns][k][lane];
            }
            float dl = 0.f;
            if (lane < 9) {
                int ty = ny - (lane / 3 - 1), tx = nx - (lane % 3 - 1);
                if (((unsigned)ty < NHH) & ((unsigned)tx < NWW))
                    dl = g_pden[b][ns][lane];
            }
#pragma unroll
            for (int o = 16; o > 0; o >>= 1)
                dl += __shfl_down_sync(0xffffffffu, dl, o);
            float den = __shfl_sync(0xffffffffu, dl, 0);
            cv = num / (den + 1e-16f);
        }
        cent_sh[w][lane] = cv;
        float cn = cv * cv;
#pragma unroll
        for (int o = 16; o > 0; o >>= 1)
            cn += __shfl_down_sync(0xffffffffu, cn, o);
        if (lane == 0) cnorm_sh[w] = cn;
    }
    __syncthreads();

    if (t < 256) {
        float dot[9];
#pragma unroll
        for (int k = 0; k < 9; k++) dot[k] = 0.f;
        float pnorm = 0.f;
#pragma unroll
        for (int c4 = 0; c4 < 8; c4++) {
            int cb = c4 * 4;
            float p0 = px_sh[t][cb],     p1 = px_sh[t][cb + 1];
            float p2 = px_sh[t][cb + 2], p3 = px_sh[t][cb + 3];
            pnorm = fmaf(p0, p0, fmaf(p1, p1, fmaf(p2, p2, fmaf(p3, p3, pnorm))));
#pragma unroll
            for (int k = 0; k < 9; k++) {
                const float4 cv = *(const float4*)&cent_sh[k][cb];
                dot[k] = fmaf(p0, cv.x, fmaf(p1, cv.y, fmaf(p2, cv.z, fmaf(p3, cv.w, dot[k]))));
            }
        }
        float d[9], dmin = 3.4e38f;
#pragma unroll
        for (int k = 0; k < 9; k++) {
            int ny = sy + k / 3 - 1, nx = sx + k % 3 - 1;
            bool v = ((unsigned)ny < NHH) & ((unsigned)nx < NWW);
            d[k] = fmaf(-2.f, dot[k], pnorm) + cnorm_sh[k];
            if (v && d[k] < dmin) dmin = d[k];
        }
        float e[9], sum = 0.f;
#pragma unroll
        for (int k = 0; k < 9; k++) {
            int ny = sy + k / 3 - 1, nx = sx + k % 3 - 1;
            bool v = ((unsigned)ny < NHH) & ((unsigned)nx < NWW);
            e[k] = v ? expf(dmin - d[k]) : 0.f;
            sum += e[k];
        }
        float inv = 1.f / sum;

        int n = (sy * SSZ + (t >> 4)) * WW + sx * SSZ + (t & 15);
        size_t obase = (size_t)b * SP * NPIX + (size_t)n;
#pragma unroll
        for (int k = 0; k < 9; k++) {
            int ny = sy + k / 3 - 1, nx = sx + k % 3 - 1;
            bool v = ((unsigned)ny < NHH) & ((unsigned)nx < NWW);
            if (v) out[obase + (size_t)(ny * NWW + nx) * NPIX] = e[k] * inv;
        }
    }
}

// ---------------------------------------------------------------------------
// E1: zero the out region OUTSIDE each sp's 3x3-tile window. Grid-stride with
// few blocks (2/SM) so the compute chain co-resides. Streaming stores.
// ---------------------------------------------------------------------------
__global__ void k_zero(float* __restrict__ out) {
    const float4 z = make_float4(0.f, 0.f, 0.f, 0.f);
    const size_t total4 = (size_t)BB * SP * NPIX / 4;
    size_t stride = (size_t)gridDim.x * blockDim.x;
    for (size_t f = (size_t)blockIdx.x * blockDim.x + threadIdx.x;
         f < total4; f += stride) {
        int i  = (int)(f & 16383);         // float4 within row
        int s  = (int)(f >> 14) & 255;
        int sy = s >> 4, sx = s & 15;
        int ty = i >> 10;                  // (i>>6)>>4 : tile row
        int tx = (i & 63) >> 2;            // ((i&63)<<2)>>4 : tile col
        unsigned dy = (unsigned)(sy - ty + 1);
        unsigned dx = (unsigned)(sx - tx + 1);
        if ((dy >= 3u) | (dx >= 3u)) __stcs((float4*)out + f, z);
    }
}

__global__ void k_tail(float* __restrict__ p, int n) {
    int i = blockIdx.x * blockDim.x + threadIdx.x;
    if (i < n) p[i] = 256.0f;
}

extern "C" void kernel_launch(void* const* d_in, const int* in_sizes, int n_in,
                              void* d_out, int out_size) {
    const float* x = (const float*)d_in[0];
    float* out = (float*)d_out;
    dim3 grid(SP, BB);

    cudaStream_t s2;
    cudaStreamCreateWithFlags(&s2, cudaStreamNonBlocking);
    cudaEvent_t e1, e2;
    cudaEventCreateWithFlags(&e1, cudaEventDisableTiming);
    cudaEventCreateWithFlags(&e2, cudaEventDisableTiming);

    cudaEventRecord(e1, 0);
    cudaStreamWaitEvent(s2, e1, 0);
    k_zero<<<296, 256, 0, s2>>>(out);      // 2 blocks/SM: saturates DRAM writes,
    cudaEventRecord(e2, s2);               // leaves room for the compute chain

    k_cent_init<<<BB * SP, 256>>>(x);
    k_iter0<<<grid, 288>>>(x);
    k_aff_out<<<grid, 288>>>(x, out);      // fused cent-update + scatter
    cudaStreamWaitEvent(0, e2, 0);         // join

    long long total = (long long)BB * SP * NPIX;
    if ((long long)out_size > total) {
        int tail = (int)((long long)out_size - total);
        k_tail<<<(tail + 255) / 256, 256>>>(out + total, tail);
    }

    cudaStreamCaptureStatus cs = cudaStreamCaptureStatusNone;
    cudaStreamIsCapturing(0, &cs);
    if (cs == cudaStreamCaptureStatusNone) {
        cudaEventDestroy(e1);
        cudaEventDestroy(e2);
        cudaStreamDestroy(s2);
    }
}

// round 7
// speedup vs baseline: 1.2375x; 1.0124x over previous
#include <cuda_runtime.h>

#define BB   4
#define CC   32
#define HH   256
#define WW   256
#define SSZ  16
#define NHH  16
#define NWW  16
#define SP   256
#define NPIX 65536

__device__ float g_cent[BB][SP][CC];
__device__ float g_pnum[BB][SP][9][CC];
__device__ float g_pden[BB][SP][9];

// ---------------------------------------------------------------------------
// A: initial centroids = 16x16 block means. One block per (b, s).
// ---------------------------------------------------------------------------
__global__ void k_cent_init(const float* __restrict__ x) {
    int bs = blockIdx.x;
    int b = bs >> 8, s = bs & 255;
    int sy = s >> 4, sx = s & 15;
    int t = threadIdx.x, warp = t >> 5, lane = t & 31;
    const float* xb = x + (size_t)b * CC * NPIX;
#pragma unroll
    for (int ci = 0; ci < 4; ci++) {
        int c = warp + ci * 8;
        const float* p = xb + (size_t)c * NPIX
                       + (size_t)(sy * SSZ + (lane >> 1)) * WW
                       + sx * SSZ + (lane & 1) * 8;
        float sum = 0.f;
#pragma unroll
        for (int i = 0; i < 8; i++) sum += p[i];
#pragma unroll
        for (int o = 16; o > 0; o >>= 1)
            sum += __shfl_down_sync(0xffffffffu, sum, o);
        if (lane == 0) g_cent[b][s][c] = sum * (1.f / 256.f);
    }
}

// ---------------------------------------------------------------------------
// B: iteration 0. 288 threads. Broadcast-float4 smem; dot-form distance.
// Per-(sp,dir) partial sums into unique slots (deterministic).
// ---------------------------------------------------------------------------
__global__ void k_iter0(const float* __restrict__ x) {
    __shared__ __align__(16) float px_sh[256][33];
    __shared__ __align__(16) float cent_sh[9][32];
    __shared__ __align__(16) float aff_sh[9][260];
    __shared__ float cnorm_sh[9];
    __shared__ float denp_sh[8][9];

    int b = blockIdx.y, s = blockIdx.x;
    int sy = s >> 4, sx = s & 15;
    int t = threadIdx.x;
    int w = t >> 5, lane = t & 31;

    if (t < 256) {
        const float* xp = x + (size_t)b * CC * NPIX
                        + (size_t)(sy * SSZ + (t >> 4)) * WW
                        + sx * SSZ + (t & 15);
#pragma unroll
        for (int c = 0; c < CC; c++) px_sh[t][c] = xp[(size_t)c * NPIX];
    }
    {
        int ny = sy + w / 3 - 1, nx = sx + w % 3 - 1;
        bool v = ((unsigned)ny < NHH) & ((unsigned)nx < NWW);
        float cv = v ? g_cent[b][ny * NWW + nx][lane] : 0.f;
        cent_sh[w][lane] = cv;
        float cn = cv * cv;
#pragma unroll
        for (int o = 16; o > 0; o >>= 1)
            cn += __shfl_down_sync(0xffffffffu, cn, o);
        if (lane == 0) cnorm_sh[w] = cn;
    }
    __syncthreads();

    if (t < 256) {
        float dot[9];
#pragma unroll
        for (int k = 0; k < 9; k++) dot[k] = 0.f;
        float pnorm = 0.f;
#pragma unroll
        for (int c4 = 0; c4 < 8; c4++) {
            int cb = c4 * 4;
            float p0 = px_sh[t][cb],     p1 = px_sh[t][cb + 1];
            float p2 = px_sh[t][cb + 2], p3 = px_sh[t][cb + 3];
            pnorm = fmaf(p0, p0, fmaf(p1, p1, fmaf(p2, p2, fmaf(p3, p3, pnorm))));
#pragma unroll
            for (int k = 0; k < 9; k++) {
                const float4 cv = *(const float4*)&cent_sh[k][cb];
                dot[k] = fmaf(p0, cv.x, fmaf(p1, cv.y, fmaf(p2, cv.z, fmaf(p3, cv.w, dot[k]))));
            }
        }
        float d[9], dmin = 3.4e38f;
#pragma unroll
        for (int k = 0; k < 9; k++) {
            int ny = sy + k / 3 - 1, nx = sx + k % 3 - 1;
            bool v = ((unsigned)ny < NHH) & ((unsigned)nx < NWW);
            d[k] = fmaf(-2.f, dot[k], pnorm) + cnorm_sh[k];
            if (v && d[k] < dmin) dmin = d[k];
        }
        float e[9], sum = 0.f;
#pragma unroll
        for (int k = 0; k < 9; k++) {
            int ny = sy + k / 3 - 1, nx = sx + k % 3 - 1;
            bool v = ((unsigned)ny < NHH) & ((unsigned)nx < NWW);
            e[k] = v ? expf(dmin - d[k]) : 0.f;
            sum += e[k];
        }
        float inv = 1.f / sum;
#pragma unroll
        for (int k = 0; k < 9; k++) aff_sh[k][t] = e[k] * inv;
    }
    __syncthreads();

    float acc[9];
#pragma unroll
    for (int k = 0; k < 9; k++) acc[k] = 0.f;
    if (t < 256) {
#pragma unroll
        for (int pg = 0; pg < 8; pg++) {
            int p = (w << 5) + (pg << 2);
            float p0 = px_sh[p][lane],     p1 = px_sh[p + 1][lane];
            float p2 = px_sh[p + 2][lane], p3 = px_sh[p + 3][lane];
#pragma unroll
            for (int k = 0; k < 9; k++) {
                const float4 a4 = *(const float4*)&aff_sh[k][p];
                acc[k] = fmaf(a4.x, p0, fmaf(a4.y, p1, fmaf(a4.z, p2, fmaf(a4.w, p3, acc[k]))));
            }
        }
        float dp[9];
#pragma unroll
        for (int k = 0; k < 9; k++) {
            float v = aff_sh[k][(w << 5) + lane];
#pragma unroll
            for (int o = 16; o > 0; o >>= 1)
                v += __shfl_down_sync(0xffffffffu, v, o);
            dp[k] = v;
        }
        if (lane == 0) {
#pragma unroll
            for (int k = 0; k < 9; k++) denp_sh[w][k] = dp[k];
        }
    }
    __syncthreads();
    float* part = &px_sh[0][0];
    if (t < 256) {
#pragma unroll
        for (int k = 0; k < 9; k++) part[(w * 9 + k) * 32 + lane] = acc[k];
    }
    __syncthreads();
    {
        int ny = sy + w / 3 - 1, nx = sx + w % 3 - 1;
        bool v = ((unsigned)ny < NHH) & ((unsigned)nx < NWW);
        if (v) {
            int ns = ny * NWW + nx;
            float num = 0.f;
#pragma unroll
            for (int ww = 0; ww < 8; ww++) num += part[(ww * 9 + w) * 32 + lane];
            g_pnum[b][ns][w][lane] = num;
            if (lane == 0) {
                float den = 0.f;
#pragma unroll
                for (int ww = 0; ww < 8; ww++) den += denp_sh[ww][w];
                g_pden[b][ns][w] = den;
            }
        }
    }
}

// ---------------------------------------------------------------------------
// D: iteration 1, fused centroid-update + softmax + direct window scatter.
// ---------------------------------------------------------------------------
__global__ void k_aff_out(const float* __restrict__ x, float* __restrict__ out) {
    __shared__ __align__(16) float px_sh[256][33];
    __shared__ __align__(16) float cent_sh[9][32];
    __shared__ float cnorm_sh[9];

    int b = blockIdx.y, s = blockIdx.x;
    int sy = s >> 4, sx = s & 15;
    int t = threadIdx.x;
    int w = t >> 5, lane = t & 31;

    if (t < 256) {
        const float* xp = x + (size_t)b * CC * NPIX
                        + (size_t)(sy * SSZ + (t >> 4)) * WW
                        + sx * SSZ + (t & 15);
#pragma unroll
        for (int c = 0; c < CC; c++) px_sh[t][c] = xp[(size_t)c * NPIX];
    }
    {
        int ny = sy + w / 3 - 1, nx = sx + w % 3 - 1;
        bool v = ((unsigned)ny < NHH) & ((unsigned)nx < NWW);
        float cv = 0.f;
        if (v) {
            int ns = ny * NWW + nx;
            float num = 0.f;
#pragma unroll
            for (int k = 0; k < 9; k++) {
                int ty = ny - (k / 3 - 1), tx = nx - (k % 3 - 1);
                if (((unsigned)ty < NHH) & ((unsigned)tx < NWW))
                    num += g_pnum[b][ns][k][lane];
            }
            float dl = 0.f;
            if (lane < 9) {
                int ty = ny - (lane / 3 - 1), tx = nx - (lane % 3 - 1);
                if (((unsigned)ty < NHH) & ((unsigned)tx < NWW))
                    dl = g_pden[b][ns][lane];
            }
#pragma unroll
            for (int o = 16; o > 0; o >>= 1)
                dl += __shfl_down_sync(0xffffffffu, dl, o);
            float den = __shfl_sync(0xffffffffu, dl, 0);
            cv = num / (den + 1e-16f);
        }
        cent_sh[w][lane] = cv;
        float cn = cv * cv;
#pragma unroll
        for (int o = 16; o > 0; o >>= 1)
            cn += __shfl_down_sync(0xffffffffu, cn, o);
        if (lane == 0) cnorm_sh[w] = cn;
    }
    __syncthreads();

    if (t < 256) {
        float dot[9];
#pragma unroll
        for (int k = 0; k < 9; k++) dot[k] = 0.f;
        float pnorm = 0.f;
#pragma unroll
        for (int c4 = 0; c4 < 8; c4++) {
            int cb = c4 * 4;
            float p0 = px_sh[t][cb],     p1 = px_sh[t][cb + 1];
            float p2 = px_sh[t][cb + 2], p3 = px_sh[t][cb + 3];
            pnorm = fmaf(p0, p0, fmaf(p1, p1, fmaf(p2, p2, fmaf(p3, p3, pnorm))));
#pragma unroll
            for (int k = 0; k < 9; k++) {
                const float4 cv = *(const float4*)&cent_sh[k][cb];
                dot[k] = fmaf(p0, cv.x, fmaf(p1, cv.y, fmaf(p2, cv.z, fmaf(p3, cv.w, dot[k]))));
            }
        }
        float d[9], dmin = 3.4e38f;
#pragma unroll
        for (int k = 0; k < 9; k++) {
            int ny = sy + k / 3 - 1, nx = sx + k % 3 - 1;
            bool v = ((unsigned)ny < NHH) & ((unsigned)nx < NWW);
            d[k] = fmaf(-2.f, dot[k], pnorm) + cnorm_sh[k];
            if (v && d[k] < dmin) dmin = d[k];
        }
        float e[9], sum = 0.f;
#pragma unroll
        for (int k = 0; k < 9; k++) {
            int ny = sy + k / 3 - 1, nx = sx + k % 3 - 1;
            bool v = ((unsigned)ny < NHH) & ((unsigned)nx < NWW);
            e[k] = v ? expf(dmin - d[k]) : 0.f;
            sum += e[k];
        }
        float inv = 1.f / sum;

        int n = (sy * SSZ + (t >> 4)) * WW + sx * SSZ + (t & 15);
        size_t obase = (size_t)b * SP * NPIX + (size_t)n;
#pragma unroll
        for (int k = 0; k < 9; k++) {
            int ny = sy + k / 3 - 1, nx = sx + k % 3 - 1;
            bool v = ((unsigned)ny < NHH) & ((unsigned)nx < NWW);
            if (v) out[obase + (size_t)(ny * NWW + nx) * NPIX] = e[k] * inv;
        }
    }
}

// ---------------------------------------------------------------------------
// E1: zero region as CONTIGUOUS segments (no per-element predicates).
// One block per (b, s); top band, bottom band, and middle left/right strips.
// Byte-disjoint from k_aff_out's windows -> safe to overlap.
// ---------------------------------------------------------------------------
__global__ void k_zero(float* __restrict__ out) {
    int b = blockIdx.y, s = blockIdx.x;
    int sy = s >> 4, sx = s & 15;
    int ny0 = max(sy - 1, 0), ny1 = min(sy + 1, NHH - 1);
    int nx0 = max(sx - 1, 0), nx1 = min(sx + 1, NWW - 1);
    int y0 = ny0 << 4, y1 = (ny1 + 1) << 4;     // window pixel-row range
    int xl4 = nx0 << 2;                          // left strip width in float4
    int xr4 = (nx1 + 1) << 2;                    // right strip start (float4)
    float4* orow = (float4*)(out + ((size_t)b * SP + s) * NPIX);
    const float4 z = make_float4(0.f, 0.f, 0.f, 0.f);
    int t = threadIdx.x;

    // Top band: float4 [0, y0*64)
    int topN = y0 << 6;
    for (int i = t; i < topN; i += 256) __stcs(orow + i, z);
    // Bottom band: float4 [y1*64, 16384)
    for (int i = (y1 << 6) + t; i < 16384; i += 256) __stcs(orow + i, z);
    // Middle strips: rows [y0,y1): left [0,xl4), right [xr4,64)
    int lw = xl4, rw = 64 - xr4, pr = lw + rw;   // float4 per middle row
    if (pr > 0) {
        int rows = y1 - y0, tot = rows * pr;
        for (int i = t; i < tot; i += 256) {
            int ry = i / pr, rx = i - ry * pr;
            int col = (rx < lw) ? rx : (xr4 + rx - lw);
            __stcs(orow + ((y0 + ry) << 6) + col, z);
        }
    }
}

__global__ void k_tail(float* __restrict__ p, int n) {
    int i = blockIdx.x * blockDim.x + threadIdx.x;
    if (i < n) p[i] = 256.0f;
}

extern "C" void kernel_launch(void* const* d_in, const int* in_sizes, int n_in,
                              void* d_out, int out_size) {
    const float* x = (const float*)d_in[0];
    float* out = (float*)d_out;
    dim3 grid(SP, BB);

    cudaStream_t s2;
    cudaStreamCreateWithFlags(&s2, cudaStreamNonBlocking);
    cudaEvent_t e1, e2;
    cudaEventCreateWithFlags(&e1, cudaEventDisableTiming);
    cudaEventCreateWithFlags(&e2, cudaEventDisableTiming);

    cudaEventRecord(e1, 0);
    cudaStreamWaitEvent(s2, e1, 0);
    k_zero<<<grid, 256, 0, s2>>>(out);     // contiguous-segment zeroing
    cudaEventRecord(e2, s2);

    k_cent_init<<<BB * SP, 256>>>(x);
    k_iter0<<<grid, 288>>>(x);
    k_aff_out<<<grid, 288>>>(x, out);      // windows: byte-disjoint from k_zero
    cudaStreamWaitEvent(0, e2, 0);         // join

    long long total = (long long)BB * SP * NPIX;
    if ((long long)out_size > total) {
        int tail = (int)((long long)out_size - total);
        k_tail<<<(tail + 255) / 256, 256>>>(out + total, tail);
    }

    cudaStreamCaptureStatus cs = cudaStreamCaptureStatusNone;
    cudaStreamIsCapturing(0, &cs);
    if (cs == cudaStreamCaptureStatusNone) {
        cudaEventDestroy(e1);
        cudaEventDestroy(e2);
        cudaStreamDestroy(s2);
    }
}